// round 3
// baseline (speedup 1.0000x reference)
#include <cuda_runtime.h>
#include <cuda_bf16.h>
#include <cstdint>

#define S_LEN  2048
#define DMODEL 4096
#define NHEADS 32
#define NKV    8
#define HDIM   128
#define KVDIM  (NKV * HDIM)   // 1024

// Scratch (allocation-free rule: __device__ globals)
__device__ float g_q[S_LEN * DMODEL];
__device__ float g_k[S_LEN * KVDIM];
__device__ float g_v[S_LEN * KVDIM];
__device__ float g_a[S_LEN * DMODEL];

// ---------------------------------------------------------------------------
// C[m,n] = sum_k A[m,k] * B[n,k]   (A: [M,K] rm, B: [N,K] rm)
// BM=BN=128, BK=16, 256 threads, 8x8 microtile
// ---------------------------------------------------------------------------
__global__ __launch_bounds__(256) void sgemm_nt(
    const float* __restrict__ A, const float* __restrict__ B,
    float* __restrict__ C, int M, int N, int K)
{
    __shared__ __align__(16) float As[16][128];
    __shared__ __align__(16) float Bs[16][128];
    const int tid = threadIdx.x;
    const int ty = tid >> 4, tx = tid & 15;
    const float* Ab = A + (size_t)blockIdx.y * 128 * K;
    const float* Bb = B + (size_t)blockIdx.x * 128 * K;

    float acc[8][8];
#pragma unroll
    for (int i = 0; i < 8; i++)
#pragma unroll
        for (int j = 0; j < 8; j++) acc[i][j] = 0.f;

    for (int k0 = 0; k0 < K; k0 += 16) {
#pragma unroll
        for (int i = 0; i < 2; i++) {
            int idx = tid + i * 256;        // 0..511
            int r   = idx >> 2;             // 0..127
            int c4  = (idx & 3) << 2;       // 0,4,8,12
            float4 va = *(const float4*)&Ab[(size_t)r * K + k0 + c4];
            As[c4 + 0][r] = va.x; As[c4 + 1][r] = va.y;
            As[c4 + 2][r] = va.z; As[c4 + 3][r] = va.w;
            float4 vb = *(const float4*)&Bb[(size_t)r * K + k0 + c4];
            Bs[c4 + 0][r] = vb.x; Bs[c4 + 1][r] = vb.y;
            Bs[c4 + 2][r] = vb.z; Bs[c4 + 3][r] = vb.w;
        }
        __syncthreads();
#pragma unroll
        for (int kk = 0; kk < 16; kk++) {
            float av[8], bv[8];
            *(float4*)&av[0] = *(const float4*)&As[kk][ty * 8];
            *(float4*)&av[4] = *(const float4*)&As[kk][ty * 8 + 4];
            *(float4*)&bv[0] = *(const float4*)&Bs[kk][tx * 8];
            *(float4*)&bv[4] = *(const float4*)&Bs[kk][tx * 8 + 4];
#pragma unroll
            for (int i = 0; i < 8; i++)
#pragma unroll
                for (int j = 0; j < 8; j++)
                    acc[i][j] = fmaf(av[i], bv[j], acc[i][j]);
        }
        __syncthreads();
    }

    const int row = blockIdx.y * 128 + ty * 8;
    const int col = blockIdx.x * 128 + tx * 8;
#pragma unroll
    for (int i = 0; i < 8; i++) {
        *(float4*)&C[(size_t)(row + i) * N + col]     = *(float4*)&acc[i][0];
        *(float4*)&C[(size_t)(row + i) * N + col + 4] = *(float4*)&acc[i][4];
    }
}

// ---------------------------------------------------------------------------
// In-place RoPE on q ([S, H*HD]) and k ([S, KV*HD]); cos/sin: [C, HD/2]
// ---------------------------------------------------------------------------
__global__ void rope_kernel(float* __restrict__ q, float* __restrict__ kk,
                            const float* __restrict__ cosb,
                            const float* __restrict__ sinb)
{
    int idx = blockIdx.x * blockDim.x + threadIdx.x;
    const int tq  = S_LEN * NHEADS * 64;
    const int tot = tq + S_LEN * NKV * 64;
    if (idx >= tot) return;

    float* base; int s, rem, stride;
    if (idx < tq) { base = q;  s = idx / (NHEADS * 64); rem = idx % (NHEADS * 64); stride = DMODEL; }
    else { int j = idx - tq; base = kk; s = j / (NKV * 64); rem = j % (NKV * 64); stride = KVDIM; }

    const int i   = rem & 63;
    const int off = s * stride + (rem >> 6) * HDIM + (i << 1);
    const float c  = cosb[s * 64 + i];
    const float sn = sinb[s * 64 + i];
    const float xr = base[off], xi = base[off + 1];
    base[off]     = xr * c - xi * sn;
    base[off + 1] = xr * sn + xi * c;
}

// ---------------------------------------------------------------------------
// Flash attention, fp32, causal, GQA (kv head = h/4)
// 1 block = 1 head x 64 q rows, 256 threads (16x16)
// smem: Qt[128][64] (d-major), KV: Kt stride 65 / V stride 132, Ps[64][66]
// ---------------------------------------------------------------------------
#define ATT_QT_F   (128 * 64)       // 8192
#define ATT_KV_F   (64 * 132)       // 8448 (>= 128*65 = 8320)
#define ATT_PS_F   (64 * 66)        // 4224
#define ATT_SMEM_B ((ATT_QT_F + ATT_KV_F + ATT_PS_F) * 4)   // 83456

__global__ __launch_bounds__(256, 2) void attn_kernel(
    const float* __restrict__ q, const float* __restrict__ k,
    const float* __restrict__ v, float* __restrict__ out)
{
    extern __shared__ __align__(16) float sm[];
    float* Qt = sm;
    float* KV = sm + ATT_QT_F;
    float* Ps = sm + ATT_QT_F + ATT_KV_F;

    const int h   = blockIdx.y;
    const int qt  = blockIdx.x;
    const int kvh = h >> 2;
    const int tid = threadIdx.x;
    const int ty  = tid >> 4, tx = tid & 15;
    const int q0  = qt * 64;

    // Load Q tile transposed: Qt[d][r], stride 64
#pragma unroll
    for (int i = 0; i < 8; i++) {
        int idx = tid + i * 256;           // 0..2047
        int r   = idx >> 5;                // 0..63
        int d4  = (idx & 31) << 2;         // 0..124
        float4 vq = *(const float4*)&q[(size_t)(q0 + r) * DMODEL + h * HDIM + d4];
        Qt[(d4 + 0) * 64 + r] = vq.x;
        Qt[(d4 + 1) * 64 + r] = vq.y;
        Qt[(d4 + 2) * 64 + r] = vq.z;
        Qt[(d4 + 3) * 64 + r] = vq.w;
    }

    float m[4], l[4], o[4][8];
#pragma unroll
    for (int i = 0; i < 4; i++) { m[i] = -1e30f; l[i] = 0.f; }
#pragma unroll
    for (int i = 0; i < 4; i++)
#pragma unroll
        for (int j = 0; j < 8; j++) o[i][j] = 0.f;

    const float scale = 0.08838834764831845f;  // 1/sqrt(128)

    for (int t = 0; t <= qt; t++) {
        const int k0 = t * 64;
        __syncthreads();  // prior V reads / Q stores done before KV overwrite

        // K tile transposed: Kt[d][j], stride 65 (odd: 4-way store conflicts only)
#pragma unroll
        for (int i = 0; i < 8; i++) {
            int idx = tid + i * 256;
            int r   = idx >> 5;
            int d4  = (idx & 31) << 2;
            float4 vk = *(const float4*)&k[(size_t)(k0 + r) * KVDIM + kvh * HDIM + d4];
            KV[(d4 + 0) * 65 + r] = vk.x;
            KV[(d4 + 1) * 65 + r] = vk.y;
            KV[(d4 + 2) * 65 + r] = vk.z;
            KV[(d4 + 3) * 65 + r] = vk.w;
        }
        __syncthreads();

        // S = Q K^T  (4x4 microtile per thread)
        float s[4][4];
#pragma unroll
        for (int ii = 0; ii < 4; ii++)
#pragma unroll
            for (int jj = 0; jj < 4; jj++) s[ii][jj] = 0.f;

#pragma unroll 4
        for (int d = 0; d < HDIM; d++) {
            float av[4];
            *(float4*)av = *(const float4*)&Qt[d * 64 + ty * 4];
            const float b0 = KV[d * 65 + tx * 4 + 0];
            const float b1 = KV[d * 65 + tx * 4 + 1];
            const float b2 = KV[d * 65 + tx * 4 + 2];
            const float b3 = KV[d * 65 + tx * 4 + 3];
#pragma unroll
            for (int ii = 0; ii < 4; ii++) {
                s[ii][0] = fmaf(av[ii], b0, s[ii][0]);
                s[ii][1] = fmaf(av[ii], b1, s[ii][1]);
                s[ii][2] = fmaf(av[ii], b2, s[ii][2]);
                s[ii][3] = fmaf(av[ii], b3, s[ii][3]);
            }
        }

        // Online softmax (rows owned across tx, reduce over 16-lane groups)
        const bool diag = (t == qt);
#pragma unroll
        for (int ii = 0; ii < 4; ii++) {
            const int grow = q0 + ty * 4 + ii;
            float sv[4];
#pragma unroll
            for (int jj = 0; jj < 4; jj++) {
                float val = s[ii][jj] * scale;
                if (diag && (k0 + tx * 4 + jj > grow)) val = -1e30f;
                sv[jj] = val;
            }
            float mx = fmaxf(fmaxf(sv[0], sv[1]), fmaxf(sv[2], sv[3]));
#pragma unroll
            for (int ofs = 1; ofs < 16; ofs <<= 1)
                mx = fmaxf(mx, __shfl_xor_sync(0xffffffffu, mx, ofs));
            const float mn = fmaxf(m[ii], mx);
            const float cf = __expf(m[ii] - mn);
            m[ii] = mn;
            float rs = 0.f;
#pragma unroll
            for (int jj = 0; jj < 4; jj++) {
                float p = __expf(sv[jj] - mn);
                Ps[(ty * 4 + ii) * 66 + tx * 4 + jj] = p;
                rs += p;
            }
#pragma unroll
            for (int ofs = 1; ofs < 16; ofs <<= 1)
                rs += __shfl_xor_sync(0xffffffffu, rs, ofs);
            l[ii] = l[ii] * cf + rs;
#pragma unroll
            for (int jj = 0; jj < 8; jj++) o[ii][jj] *= cf;
        }
        __syncthreads();  // Ps written, Kt reads done

        // V tile row-major: V[j][d], stride 132 (float4-aligned)
#pragma unroll
        for (int i = 0; i < 8; i++) {
            int idx = tid + i * 256;
            int r   = idx >> 5;
            int d4  = (idx & 31) << 2;
            float4 vv = *(const float4*)&v[(size_t)(k0 + r) * KVDIM + kvh * HDIM + d4];
            *(float4*)&KV[r * 132 + d4] = vv;
        }
        __syncthreads();

        // O += P @ V  (4 rows x 8 cols per thread)
#pragma unroll 2
        for (int j = 0; j < 64; j++) {
            const float p0 = Ps[(ty * 4 + 0) * 66 + j];
            const float p1 = Ps[(ty * 4 + 1) * 66 + j];
            const float p2 = Ps[(ty * 4 + 2) * 66 + j];
            const float p3 = Ps[(ty * 4 + 3) * 66 + j];
            float vv[8];
            *(float4*)&vv[0] = *(const float4*)&KV[j * 132 + tx * 8];
            *(float4*)&vv[4] = *(const float4*)&KV[j * 132 + tx * 8 + 4];
#pragma unroll
            for (int jj = 0; jj < 8; jj++) {
                o[0][jj] = fmaf(p0, vv[jj], o[0][jj]);
                o[1][jj] = fmaf(p1, vv[jj], o[1][jj]);
                o[2][jj] = fmaf(p2, vv[jj], o[2][jj]);
                o[3][jj] = fmaf(p3, vv[jj], o[3][jj]);
            }
        }
    }

    // Normalize and store: out[s, h*128 + d]
#pragma unroll
    for (int ii = 0; ii < 4; ii++) {
        const float inv = 1.0f / l[ii];
        float res[8];
#pragma unroll
        for (int jj = 0; jj < 8; jj++) res[jj] = o[ii][jj] * inv;
        size_t base = (size_t)(q0 + ty * 4 + ii) * DMODEL + h * HDIM + tx * 8;
        *(float4*)&out[base]     = *(float4*)&res[0];
        *(float4*)&out[base + 4] = *(float4*)&res[4];
    }
}

// ---------------------------------------------------------------------------
extern "C" void kernel_launch(void* const* d_in, const int* in_sizes, int n_in,
                              void* d_out, int out_size)
{
    const float* x    = (const float*)d_in[0];
    const float* wq   = (const float*)d_in[1];
    const float* wk   = (const float*)d_in[2];
    const float* wv   = (const float*)d_in[3];
    const float* wo   = (const float*)d_in[4];
    const float* cosb = (const float*)d_in[7];
    const float* sinb = (const float*)d_in[8];
    float* out = (float*)d_out;

    float *q, *k, *v, *a;
    cudaGetSymbolAddress((void**)&q, g_q);
    cudaGetSymbolAddress((void**)&k, g_k);
    cudaGetSymbolAddress((void**)&v, g_v);
    cudaGetSymbolAddress((void**)&a, g_a);

    // Projections: q = x wq^T, k = x wk^T, v = x wv^T
    sgemm_nt<<<dim3(DMODEL / 128, S_LEN / 128), 256>>>(x, wq, q, S_LEN, DMODEL, DMODEL);
    sgemm_nt<<<dim3(KVDIM  / 128, S_LEN / 128), 256>>>(x, wk, k, S_LEN, KVDIM,  DMODEL);
    sgemm_nt<<<dim3(KVDIM  / 128, S_LEN / 128), 256>>>(x, wv, v, S_LEN, KVDIM,  DMODEL);

    const int pairs = S_LEN * NHEADS * 64 + S_LEN * NKV * 64;
    rope_kernel<<<(pairs + 255) / 256, 256>>>(q, k, cosb, sinb);

    cudaFuncSetAttribute(attn_kernel, cudaFuncAttributeMaxDynamicSharedMemorySize, ATT_SMEM_B);
    attn_kernel<<<dim3(S_LEN / 64, NHEADS), 256, ATT_SMEM_B>>>(q, k, v, a);

    // Output projection: out = a wo^T
    sgemm_nt<<<dim3(DMODEL / 128, S_LEN / 128), 256>>>(a, wo, out, S_LEN, DMODEL, DMODEL);
}

// round 11
// speedup vs baseline: 1.1447x; 1.1447x over previous
#include <cuda_runtime.h>
#include <cuda_bf16.h>
#include <cstdint>

#define S_LEN  2048
#define DMODEL 4096
#define NHEADS 32
#define NKV    8
#define HDIM   128
#define KVDIM  (NKV * HDIM)   // 1024

// ---------------- scratch (__device__ globals; no allocs allowed) ----------
__device__ float g_q[S_LEN * DMODEL];
__device__ float g_k[S_LEN * KVDIM];
__device__ float g_v[S_LEN * KVDIM];
__device__ float g_a[S_LEN * DMODEL];

__device__ __nv_bfloat16 g_xh[S_LEN * DMODEL],  g_xl[S_LEN * DMODEL];
__device__ __nv_bfloat16 g_ah[S_LEN * DMODEL],  g_al[S_LEN * DMODEL];
__device__ __nv_bfloat16 g_wqh[DMODEL * DMODEL], g_wql[DMODEL * DMODEL];
__device__ __nv_bfloat16 g_wkh[KVDIM * DMODEL],  g_wkl[KVDIM * DMODEL];
__device__ __nv_bfloat16 g_wvh[KVDIM * DMODEL],  g_wvl[KVDIM * DMODEL];
__device__ __nv_bfloat16 g_woh[DMODEL * DMODEL], g_wol[DMODEL * DMODEL];

// ---------------- PTX helpers (baseline ISA only; no sm_103a features) -----
__device__ __forceinline__ uint32_t smem_u32(const void* p) {
    uint32_t a;
    asm("{ .reg .u64 t; cvta.to.shared.u64 t, %1; cvt.u32.u64 %0, t; }" : "=r"(a) : "l"(p));
    return a;
}
#define CP_ASYNC16(dst, src) asm volatile("cp.async.cg.shared.global [%0], [%1], 16;" :: "r"(dst), "l"(src) : "memory")
#define CP_COMMIT()          asm volatile("cp.async.commit_group;" ::: "memory")
#define CP_WAIT1()           asm volatile("cp.async.wait_group 1;" ::: "memory")
#define CP_WAIT0()           asm volatile("cp.async.wait_group 0;" ::: "memory")

#define LDSM4(r0, r1, r2, r3, addr) \
    asm volatile("ldmatrix.sync.aligned.m8n8.x4.shared.b16 {%0,%1,%2,%3}, [%4];" \
        : "=r"(r0), "=r"(r1), "=r"(r2), "=r"(r3) : "r"(addr))

#define MMA16816(c, a0, a1, a2, a3, b0, b1) \
    asm volatile("mma.sync.aligned.m16n8k16.row.col.f32.bf16.bf16.f32 " \
        "{%0,%1,%2,%3}, {%4,%5,%6,%7}, {%8,%9}, {%0,%1,%2,%3};" \
        : "+f"((c)[0]), "+f"((c)[1]), "+f"((c)[2]), "+f"((c)[3]) \
        : "r"(a0), "r"(a1), "r"(a2), "r"(a3), "r"(b0), "r"(b1))

// ---------------------------------------------------------------------------
// split: fp32 -> (hi bf16, lo bf16)
// ---------------------------------------------------------------------------
__global__ void split_kernel(const float* __restrict__ src,
                             __nv_bfloat16* __restrict__ hi,
                             __nv_bfloat16* __restrict__ lo, int n)
{
    int i = (blockIdx.x * blockDim.x + threadIdx.x) * 4;
    if (i >= n) return;
    float4 v = *(const float4*)(src + i);
    float vv[4] = {v.x, v.y, v.z, v.w};
    __nv_bfloat16 h[4], l[4];
#pragma unroll
    for (int j = 0; j < 4; j++) {
        h[j] = __float2bfloat16(vv[j]);
        l[j] = __float2bfloat16(vv[j] - __bfloat162float(h[j]));
    }
    *(__nv_bfloat162*)&hi[i]     = __nv_bfloat162(h[0], h[1]);
    *(__nv_bfloat162*)&hi[i + 2] = __nv_bfloat162(h[2], h[3]);
    *(__nv_bfloat162*)&lo[i]     = __nv_bfloat162(l[0], l[1]);
    *(__nv_bfloat162*)&lo[i + 2] = __nv_bfloat162(l[2], l[3]);
}

// ---------------------------------------------------------------------------
// Split-bf16 mma.sync GEMM: C[m,n] = sum_k A[m,k]*B[n,k]
// CTA tile 128x128, K-chunk 32, 8 warps (warp tile 64x32), double buffer.
// SMEM rows: 32 bf16 = 64B data at 80B stride (5 granules -> ldmatrix
// conflict-free: (5r+c) mod 8 distinct over 8 rows).
// ---------------------------------------------------------------------------
#define GT_STRIDE  80
#define GT_TILE_B  (128 * GT_STRIDE)     // 10240
#define GT_STAGE_B (4 * GT_TILE_B)       // 40960
#define GT_SMEM_B  (2 * GT_STAGE_B)      // 81920

__global__ __launch_bounds__(256, 1) void gemm_mma(
    const __nv_bfloat16* __restrict__ Ah, const __nv_bfloat16* __restrict__ Al,
    const __nv_bfloat16* __restrict__ Bh, const __nv_bfloat16* __restrict__ Bl,
    float* __restrict__ C, int N, int K)
{
    extern __shared__ char smem[];
    const uint32_t sbase = smem_u32(smem);
    const int tid  = threadIdx.x;
    const int wid  = tid >> 5, lane = tid & 31;
    const int m0   = blockIdx.y << 7, n0 = blockIdx.x << 7;
    const int wm   = (wid & 1) << 6;        // warp m offset: 0 / 64
    const int wn   = (wid >> 1) << 5;       // warp n offset: 0,32,64,96
    const size_t Kb = (size_t)K * 2;

    const char* srcs[4] = {(const char*)Ah, (const char*)Al,
                           (const char*)Bh, (const char*)Bl};
    const int   rb[4]   = {m0, m0, n0, n0};

    float acc[4][4][4];
#pragma unroll
    for (int i = 0; i < 4; i++)
#pragma unroll
        for (int j = 0; j < 4; j++)
#pragma unroll
            for (int r = 0; r < 4; r++) acc[i][j][r] = 0.f;

    // ---- chunk loader: 4 tiles x 128 rows x 64B, 16B granules -------------
    auto load_chunk = [&](int c, uint32_t stage) {
#pragma unroll
        for (int i = 0; i < 8; i++) {
            const int t   = i >> 1;                     // tile 0..3
            const int g   = tid + ((i & 1) << 8);       // granule 0..511
            const int row = g >> 2;
            const int col = (g & 3) << 4;
            const char* src = srcs[t] + (size_t)(rb[t] + row) * Kb
                              + (size_t)c * 64 + col;
            CP_ASYNC16(stage + t * GT_TILE_B + row * GT_STRIDE + col, src);
        }
    };

    const int nchunk = K >> 5;
    load_chunk(0, sbase);
    CP_COMMIT();

    // ldmatrix lane address components
    const int lm  = lane & 7;
    const int grp = lane >> 3;
    const int a_row = wm + ((grp & 1) << 3) + lm;       // + mt*16
    const int a_colg = (grp >> 1) << 4;                 // + step*32
    const int b_row = wn + ((grp >> 1) << 3) + lm;      // + pair*16
    const int b_colg = (grp & 1) << 4;                  // + step*32

    for (int c = 0; c < nchunk; c++) {
        const uint32_t st = sbase + (uint32_t)(c & 1) * GT_STAGE_B;
        if (c + 1 < nchunk) {
            load_chunk(c + 1, sbase + (uint32_t)((c + 1) & 1) * GT_STAGE_B);
            CP_COMMIT();
            CP_WAIT1();
        } else {
            CP_WAIT0();
        }
        __syncthreads();

#pragma unroll
        for (int step = 0; step < 2; step++) {
            const int kcol = step << 5;
            uint32_t ah[4][4], al[4][4], bh[2][4], bl[2][4];
#pragma unroll
            for (int mt = 0; mt < 4; mt++) {
                uint32_t ra = st + (a_row + mt * 16) * GT_STRIDE + kcol + a_colg;
                LDSM4(ah[mt][0], ah[mt][1], ah[mt][2], ah[mt][3], ra);
                LDSM4(al[mt][0], al[mt][1], al[mt][2], al[mt][3], ra + GT_TILE_B);
            }
#pragma unroll
            for (int pr = 0; pr < 2; pr++) {
                uint32_t rbb = st + 2 * GT_TILE_B
                               + (b_row + pr * 16) * GT_STRIDE + kcol + b_colg;
                LDSM4(bh[pr][0], bh[pr][1], bh[pr][2], bh[pr][3], rbb);
                LDSM4(bl[pr][0], bl[pr][1], bl[pr][2], bl[pr][3], rbb + GT_TILE_B);
            }
#pragma unroll
            for (int mt = 0; mt < 4; mt++)
#pragma unroll
                for (int nt = 0; nt < 4; nt++) {
                    const int pr = nt >> 1, hl = (nt & 1) << 1;
                    MMA16816(acc[mt][nt], ah[mt][0], ah[mt][1], ah[mt][2], ah[mt][3],
                             bh[pr][hl], bh[pr][hl + 1]);
                    MMA16816(acc[mt][nt], al[mt][0], al[mt][1], al[mt][2], al[mt][3],
                             bh[pr][hl], bh[pr][hl + 1]);
                    MMA16816(acc[mt][nt], ah[mt][0], ah[mt][1], ah[mt][2], ah[mt][3],
                             bl[pr][hl], bl[pr][hl + 1]);
                }
        }
        __syncthreads();
    }

    // ---- epilogue ----------------------------------------------------------
    const int crow = lane >> 2;
    const int ccol = (lane & 3) << 1;
#pragma unroll
    for (int mt = 0; mt < 4; mt++)
#pragma unroll
        for (int nt = 0; nt < 4; nt++) {
            const int r = m0 + wm + mt * 16 + crow;
            const int cc = n0 + wn + nt * 8 + ccol;
            *(float2*)&C[(size_t)r * N + cc]       = make_float2(acc[mt][nt][0], acc[mt][nt][1]);
            *(float2*)&C[(size_t)(r + 8) * N + cc] = make_float2(acc[mt][nt][2], acc[mt][nt][3]);
        }
}

// ---------------------------------------------------------------------------
// In-place RoPE on q ([S, H*HD]) and k ([S, KV*HD]); cos/sin: [C, HD/2]
// ---------------------------------------------------------------------------
__global__ void rope_kernel(float* __restrict__ q, float* __restrict__ kk,
                            const float* __restrict__ cosb,
                            const float* __restrict__ sinb)
{
    int idx = blockIdx.x * blockDim.x + threadIdx.x;
    const int tq  = S_LEN * NHEADS * 64;
    const int tot = tq + S_LEN * NKV * 64;
    if (idx >= tot) return;

    float* base; int s, rem, stride;
    if (idx < tq) { base = q;  s = idx / (NHEADS * 64); rem = idx % (NHEADS * 64); stride = DMODEL; }
    else { int j = idx - tq; base = kk; s = j / (NKV * 64); rem = j % (NKV * 64); stride = KVDIM; }

    const int i   = rem & 63;
    const int off = s * stride + (rem >> 6) * HDIM + (i << 1);
    const float c  = cosb[s * 64 + i];
    const float sn = sinb[s * 64 + i];
    const float xr = base[off], xi = base[off + 1];
    base[off]     = xr * c - xi * sn;
    base[off + 1] = xr * sn + xi * c;
}

// ---------------------------------------------------------------------------
// Flash attention, fp32, causal, GQA (kv head = h/4)  [validated baseline]
// ---------------------------------------------------------------------------
#define ATT_QT_F   (128 * 64)
#define ATT_KV_F   (64 * 132)
#define ATT_PS_F   (64 * 66)
#define ATT_SMEM_B ((ATT_QT_F + ATT_KV_F + ATT_PS_F) * 4)

__global__ __launch_bounds__(256, 2) void attn_kernel(
    const float* __restrict__ q, const float* __restrict__ k,
    const float* __restrict__ v, float* __restrict__ out)
{
    extern __shared__ __align__(16) float sm[];
    float* Qt = sm;
    float* KV = sm + ATT_QT_F;
    float* Ps = sm + ATT_QT_F + ATT_KV_F;

    const int h   = blockIdx.y;
    const int qt  = blockIdx.x;
    const int kvh = h >> 2;
    const int tid = threadIdx.x;
    const int ty  = tid >> 4, tx = tid & 15;
    const int q0  = qt * 64;

#pragma unroll
    for (int i = 0; i < 8; i++) {
        int idx = tid + i * 256;
        int r   = idx >> 5;
        int d4  = (idx & 31) << 2;
        float4 vq = *(const float4*)&q[(size_t)(q0 + r) * DMODEL + h * HDIM + d4];
        Qt[(d4 + 0) * 64 + r] = vq.x;
        Qt[(d4 + 1) * 64 + r] = vq.y;
        Qt[(d4 + 2) * 64 + r] = vq.z;
        Qt[(d4 + 3) * 64 + r] = vq.w;
    }

    float m[4], l[4], o[4][8];
#pragma unroll
    for (int i = 0; i < 4; i++) { m[i] = -1e30f; l[i] = 0.f; }
#pragma unroll
    for (int i = 0; i < 4; i++)
#pragma unroll
        for (int j = 0; j < 8; j++) o[i][j] = 0.f;

    const float scale = 0.08838834764831845f;

    for (int t = 0; t <= qt; t++) {
        const int k0 = t * 64;
        __syncthreads();

#pragma unroll
        for (int i = 0; i < 8; i++) {
            int idx = tid + i * 256;
            int r   = idx >> 5;
            int d4  = (idx & 31) << 2;
            float4 vk = *(const float4*)&k[(size_t)(k0 + r) * KVDIM + kvh * HDIM + d4];
            KV[(d4 + 0) * 65 + r] = vk.x;
            KV[(d4 + 1) * 65 + r] = vk.y;
            KV[(d4 + 2) * 65 + r] = vk.z;
            KV[(d4 + 3) * 65 + r] = vk.w;
        }
        __syncthreads();

        float s[4][4];
#pragma unroll
        for (int ii = 0; ii < 4; ii++)
#pragma unroll
            for (int jj = 0; jj < 4; jj++) s[ii][jj] = 0.f;

#pragma unroll 4
        for (int d = 0; d < HDIM; d++) {
            float av[4];
            *(float4*)av = *(const float4*)&Qt[d * 64 + ty * 4];
            const float b0 = KV[d * 65 + tx * 4 + 0];
            const float b1 = KV[d * 65 + tx * 4 + 1];
            const float b2 = KV[d * 65 + tx * 4 + 2];
            const float b3 = KV[d * 65 + tx * 4 + 3];
#pragma unroll
            for (int ii = 0; ii < 4; ii++) {
                s[ii][0] = fmaf(av[ii], b0, s[ii][0]);
                s[ii][1] = fmaf(av[ii], b1, s[ii][1]);
                s[ii][2] = fmaf(av[ii], b2, s[ii][2]);
                s[ii][3] = fmaf(av[ii], b3, s[ii][3]);
            }
        }

        const bool diag = (t == qt);
#pragma unroll
        for (int ii = 0; ii < 4; ii++) {
            const int grow = q0 + ty * 4 + ii;
            float sv[4];
#pragma unroll
            for (int jj = 0; jj < 4; jj++) {
                float val = s[ii][jj] * scale;
                if (diag && (k0 + tx * 4 + jj > grow)) val = -1e30f;
                sv[jj] = val;
            }
            float mx = fmaxf(fmaxf(sv[0], sv[1]), fmaxf(sv[2], sv[3]));
#pragma unroll
            for (int ofs = 1; ofs < 16; ofs <<= 1)
                mx = fmaxf(mx, __shfl_xor_sync(0xffffffffu, mx, ofs));
            const float mn = fmaxf(m[ii], mx);
            const float cf = __expf(m[ii] - mn);
            m[ii] = mn;
            float rs = 0.f;
#pragma unroll
            for (int jj = 0; jj < 4; jj++) {
                float p = __expf(sv[jj] - mn);
                Ps[(ty * 4 + ii) * 66 + tx * 4 + jj] = p;
                rs += p;
            }
#pragma unroll
            for (int ofs = 1; ofs < 16; ofs <<= 1)
                rs += __shfl_xor_sync(0xffffffffu, rs, ofs);
            l[ii] = l[ii] * cf + rs;
#pragma unroll
            for (int jj = 0; jj < 8; jj++) o[ii][jj] *= cf;
        }
        __syncthreads();

#pragma unroll
        for (int i = 0; i < 8; i++) {
            int idx = tid + i * 256;
            int r   = idx >> 5;
            int d4  = (idx & 31) << 2;
            float4 vv = *(const float4*)&v[(size_t)(k0 + r) * KVDIM + kvh * HDIM + d4];
            *(float4*)&KV[r * 132 + d4] = vv;
        }
        __syncthreads();

#pragma unroll 2
        for (int j = 0; j < 64; j++) {
            const float p0 = Ps[(ty * 4 + 0) * 66 + j];
            const float p1 = Ps[(ty * 4 + 1) * 66 + j];
            const float p2 = Ps[(ty * 4 + 2) * 66 + j];
            const float p3 = Ps[(ty * 4 + 3) * 66 + j];
            float vv[8];
            *(float4*)&vv[0] = *(const float4*)&KV[j * 132 + tx * 8];
            *(float4*)&vv[4] = *(const float4*)&KV[j * 132 + tx * 8 + 4];
#pragma unroll
            for (int jj = 0; jj < 8; jj++) {
                o[0][jj] = fmaf(p0, vv[jj], o[0][jj]);
                o[1][jj] = fmaf(p1, vv[jj], o[1][jj]);
                o[2][jj] = fmaf(p2, vv[jj], o[2][jj]);
                o[3][jj] = fmaf(p3, vv[jj], o[3][jj]);
            }
        }
    }

#pragma unroll
    for (int ii = 0; ii < 4; ii++) {
        const float inv = 1.0f / l[ii];
        float res[8];
#pragma unroll
        for (int jj = 0; jj < 8; jj++) res[jj] = o[ii][jj] * inv;
        size_t base = (size_t)(q0 + ty * 4 + ii) * DMODEL + h * HDIM + tx * 8;
        *(float4*)&out[base]     = *(float4*)&res[0];
        *(float4*)&out[base + 4] = *(float4*)&res[4];
    }
}

// ---------------------------------------------------------------------------
extern "C" void kernel_launch(void* const* d_in, const int* in_sizes, int n_in,
                              void* d_out, int out_size)
{
    const float* x    = (const float*)d_in[0];
    const float* wq   = (const float*)d_in[1];
    const float* wk   = (const float*)d_in[2];
    const float* wv   = (const float*)d_in[3];
    const float* wo   = (const float*)d_in[4];
    const float* cosb = (const float*)d_in[7];
    const float* sinb = (const float*)d_in[8];
    float* out = (float*)d_out;

    float *q, *k, *v, *a;
    cudaGetSymbolAddress((void**)&q, g_q);
    cudaGetSymbolAddress((void**)&k, g_k);
    cudaGetSymbolAddress((void**)&v, g_v);
    cudaGetSymbolAddress((void**)&a, g_a);
    __nv_bfloat16 *xh, *xl, *ah, *al, *wqh, *wql, *wkh, *wkl, *wvh, *wvl, *woh, *wol;
    cudaGetSymbolAddress((void**)&xh, g_xh);   cudaGetSymbolAddress((void**)&xl, g_xl);
    cudaGetSymbolAddress((void**)&ah, g_ah);   cudaGetSymbolAddress((void**)&al, g_al);
    cudaGetSymbolAddress((void**)&wqh, g_wqh); cudaGetSymbolAddress((void**)&wql, g_wql);
    cudaGetSymbolAddress((void**)&wkh, g_wkh); cudaGetSymbolAddress((void**)&wkl, g_wkl);
    cudaGetSymbolAddress((void**)&wvh, g_wvh); cudaGetSymbolAddress((void**)&wvl, g_wvl);
    cudaGetSymbolAddress((void**)&woh, g_woh); cudaGetSymbolAddress((void**)&wol, g_wol);

    cudaFuncSetAttribute(gemm_mma, cudaFuncAttributeMaxDynamicSharedMemorySize, GT_SMEM_B);
    cudaFuncSetAttribute(attn_kernel, cudaFuncAttributeMaxDynamicSharedMemorySize, ATT_SMEM_B);

    // fp32 -> split-bf16 conversions
    const int nx = S_LEN * DMODEL, nwq = DMODEL * DMODEL, nwk = KVDIM * DMODEL;
    split_kernel<<<nx  / 1024, 256>>>(x,  xh,  xl,  nx);
    split_kernel<<<nwq / 1024, 256>>>(wq, wqh, wql, nwq);
    split_kernel<<<nwk / 1024, 256>>>(wk, wkh, wkl, nwk);
    split_kernel<<<nwk / 1024, 256>>>(wv, wvh, wvl, nwk);
    split_kernel<<<nwq / 1024, 256>>>(wo, woh, wol, nwq);

    // Projections on tensor cores (mma.sync HMMA path)
    gemm_mma<<<dim3(DMODEL / 128, S_LEN / 128), 256, GT_SMEM_B>>>(xh, xl, wqh, wql, q, DMODEL, DMODEL);
    gemm_mma<<<dim3(KVDIM  / 128, S_LEN / 128), 256, GT_SMEM_B>>>(xh, xl, wkh, wkl, k, KVDIM,  DMODEL);
    gemm_mma<<<dim3(KVDIM  / 128, S_LEN / 128), 256, GT_SMEM_B>>>(xh, xl, wvh, wvl, v, KVDIM,  DMODEL);

    const int pairs = S_LEN * NHEADS * 64 + S_LEN * NKV * 64;
    rope_kernel<<<(pairs + 255) / 256, 256>>>(q, k, cosb, sinb);

    attn_kernel<<<dim3(S_LEN / 64, NHEADS), 256, ATT_SMEM_B>>>(q, k, v, a);

    // Output projection
    split_kernel<<<nx / 1024, 256>>>(a, ah, al, nx);
    gemm_mma<<<dim3(DMODEL / 128, S_LEN / 128), 256, GT_SMEM_B>>>(ah, al, woh, wol, out, DMODEL, DMODEL);
}

// round 14
// speedup vs baseline: 3.0027x; 2.6232x over previous
#include <cuda_runtime.h>
#include <cuda_bf16.h>
#include <cstdint>

#define S_LEN  2048
#define DMODEL 4096
#define NHEADS 32
#define NKV    8
#define HDIM   128
#define KVDIM  (NKV * HDIM)   // 1024

// ---------------- scratch (__device__ globals; no allocs allowed) ----------
__device__ float g_q[S_LEN * DMODEL];
__device__ float g_k[S_LEN * KVDIM];
__device__ float g_v[S_LEN * KVDIM];
__device__ float g_a[S_LEN * DMODEL];

__device__ __nv_bfloat16 g_xh[S_LEN * DMODEL],  g_xl[S_LEN * DMODEL];
__device__ __nv_bfloat16 g_ah[S_LEN * DMODEL],  g_al[S_LEN * DMODEL];
__device__ __nv_bfloat16 g_wqh[DMODEL * DMODEL], g_wql[DMODEL * DMODEL];
__device__ __nv_bfloat16 g_wkh[KVDIM * DMODEL],  g_wkl[KVDIM * DMODEL];
__device__ __nv_bfloat16 g_wvh[KVDIM * DMODEL],  g_wvl[KVDIM * DMODEL];
__device__ __nv_bfloat16 g_woh[DMODEL * DMODEL], g_wol[DMODEL * DMODEL];
// attention split buffers
__device__ __nv_bfloat16 g_qh2[S_LEN * DMODEL], g_ql2[S_LEN * DMODEL];
__device__ __nv_bfloat16 g_kh2[S_LEN * KVDIM],  g_kl2[S_LEN * KVDIM];
__device__ __nv_bfloat16 g_vh2[S_LEN * KVDIM],  g_vl2[S_LEN * KVDIM];

// ---------------- PTX helpers (baseline ISA only; no sm_103a features) -----
__device__ __forceinline__ uint32_t smem_u32(const void* p) {
    uint32_t a;
    asm("{ .reg .u64 t; cvta.to.shared.u64 t, %1; cvt.u32.u64 %0, t; }" : "=r"(a) : "l"(p));
    return a;
}
#define CP_ASYNC16(dst, src) asm volatile("cp.async.cg.shared.global [%0], [%1], 16;" :: "r"(dst), "l"(src) : "memory")
#define CP_COMMIT()          asm volatile("cp.async.commit_group;" ::: "memory")
#define CP_WAIT1()           asm volatile("cp.async.wait_group 1;" ::: "memory")
#define CP_WAIT0()           asm volatile("cp.async.wait_group 0;" ::: "memory")

#define LDSM4(r0, r1, r2, r3, addr) \
    asm volatile("ldmatrix.sync.aligned.m8n8.x4.shared.b16 {%0,%1,%2,%3}, [%4];" \
        : "=r"(r0), "=r"(r1), "=r"(r2), "=r"(r3) : "r"(addr))
#define LDSM4T(r0, r1, r2, r3, addr) \
    asm volatile("ldmatrix.sync.aligned.m8n8.x4.trans.shared.b16 {%0,%1,%2,%3}, [%4];" \
        : "=r"(r0), "=r"(r1), "=r"(r2), "=r"(r3) : "r"(addr))

#define MMA16816(c, a0, a1, a2, a3, b0, b1) \
    asm volatile("mma.sync.aligned.m16n8k16.row.col.f32.bf16.bf16.f32 " \
        "{%0,%1,%2,%3}, {%4,%5,%6,%7}, {%8,%9}, {%0,%1,%2,%3};" \
        : "+f"((c)[0]), "+f"((c)[1]), "+f"((c)[2]), "+f"((c)[3]) \
        : "r"(a0), "r"(a1), "r"(a2), "r"(a3), "r"(b0), "r"(b1))

// pack two fp32 -> split bf16x2 pair (lo element first)
__device__ __forceinline__ void splitpack(float p0, float p1, uint32_t& hreg, uint32_t& lreg) {
    __nv_bfloat16 h0 = __float2bfloat16(p0), h1 = __float2bfloat16(p1);
    float l0 = p0 - __bfloat162float(h0), l1 = p1 - __bfloat162float(h1);
    __nv_bfloat162 hh(h0, h1);
    __nv_bfloat162 ll(__float2bfloat16(l0), __float2bfloat16(l1));
    hreg = *(uint32_t*)&hh;
    lreg = *(uint32_t*)&ll;
}

// ---------------------------------------------------------------------------
// split: fp32 -> (hi bf16, lo bf16)
// ---------------------------------------------------------------------------
__global__ void split_kernel(const float* __restrict__ src,
                             __nv_bfloat16* __restrict__ hi,
                             __nv_bfloat16* __restrict__ lo, int n)
{
    int i = (blockIdx.x * blockDim.x + threadIdx.x) * 4;
    if (i >= n) return;
    float4 v = *(const float4*)(src + i);
    float vv[4] = {v.x, v.y, v.z, v.w};
    __nv_bfloat16 h[4], l[4];
#pragma unroll
    for (int j = 0; j < 4; j++) {
        h[j] = __float2bfloat16(vv[j]);
        l[j] = __float2bfloat16(vv[j] - __bfloat162float(h[j]));
    }
    *(__nv_bfloat162*)&hi[i]     = __nv_bfloat162(h[0], h[1]);
    *(__nv_bfloat162*)&hi[i + 2] = __nv_bfloat162(h[2], h[3]);
    *(__nv_bfloat162*)&lo[i]     = __nv_bfloat162(l[0], l[1]);
    *(__nv_bfloat162*)&lo[i + 2] = __nv_bfloat162(l[2], l[3]);
}

// ---------------------------------------------------------------------------
// Split-bf16 mma.sync GEMM (validated) — 2 CTAs/SM
// ---------------------------------------------------------------------------
#define GT_STRIDE  80
#define GT_TILE_B  (128 * GT_STRIDE)
#define GT_STAGE_B (4 * GT_TILE_B)
#define GT_SMEM_B  (2 * GT_STAGE_B)

__global__ __launch_bounds__(256, 2) void gemm_mma(
    const __nv_bfloat16* __restrict__ Ah, const __nv_bfloat16* __restrict__ Al,
    const __nv_bfloat16* __restrict__ Bh, const __nv_bfloat16* __restrict__ Bl,
    float* __restrict__ C, int N, int K)
{
    extern __shared__ char smem[];
    const uint32_t sbase = smem_u32(smem);
    const int tid  = threadIdx.x;
    const int wid  = tid >> 5, lane = tid & 31;
    const int m0   = blockIdx.y << 7, n0 = blockIdx.x << 7;
    const int wm   = (wid & 1) << 6;
    const int wn   = (wid >> 1) << 5;
    const size_t Kb = (size_t)K * 2;

    const char* srcs[4] = {(const char*)Ah, (const char*)Al,
                           (const char*)Bh, (const char*)Bl};
    const int   rb[4]   = {m0, m0, n0, n0};

    float acc[4][4][4];
#pragma unroll
    for (int i = 0; i < 4; i++)
#pragma unroll
        for (int j = 0; j < 4; j++)
#pragma unroll
            for (int r = 0; r < 4; r++) acc[i][j][r] = 0.f;

    auto load_chunk = [&](int c, uint32_t stage) {
#pragma unroll
        for (int i = 0; i < 8; i++) {
            const int t   = i >> 1;
            const int g   = tid + ((i & 1) << 8);
            const int row = g >> 2;
            const int col = (g & 3) << 4;
            const char* src = srcs[t] + (size_t)(rb[t] + row) * Kb
                              + (size_t)c * 64 + col;
            CP_ASYNC16(stage + t * GT_TILE_B + row * GT_STRIDE + col, src);
        }
    };

    const int nchunk = K >> 5;
    load_chunk(0, sbase);
    CP_COMMIT();

    const int lm  = lane & 7;
    const int grp = lane >> 3;
    const int a_row = wm + ((grp & 1) << 3) + lm;
    const int a_colg = (grp >> 1) << 4;
    const int b_row = wn + ((grp >> 1) << 3) + lm;
    const int b_colg = (grp & 1) << 4;

    for (int c = 0; c < nchunk; c++) {
        const uint32_t st = sbase + (uint32_t)(c & 1) * GT_STAGE_B;
        if (c + 1 < nchunk) {
            load_chunk(c + 1, sbase + (uint32_t)((c + 1) & 1) * GT_STAGE_B);
            CP_COMMIT();
            CP_WAIT1();
        } else {
            CP_WAIT0();
        }
        __syncthreads();

#pragma unroll
        for (int step = 0; step < 2; step++) {
            const int kcol = step << 5;
            uint32_t ah[4][4], al[4][4], bh[2][4], bl[2][4];
#pragma unroll
            for (int mt = 0; mt < 4; mt++) {
                uint32_t ra = st + (a_row + mt * 16) * GT_STRIDE + kcol + a_colg;
                LDSM4(ah[mt][0], ah[mt][1], ah[mt][2], ah[mt][3], ra);
                LDSM4(al[mt][0], al[mt][1], al[mt][2], al[mt][3], ra + GT_TILE_B);
            }
#pragma unroll
            for (int pr = 0; pr < 2; pr++) {
                uint32_t rbb = st + 2 * GT_TILE_B
                               + (b_row + pr * 16) * GT_STRIDE + kcol + b_colg;
                LDSM4(bh[pr][0], bh[pr][1], bh[pr][2], bh[pr][3], rbb);
                LDSM4(bl[pr][0], bl[pr][1], bl[pr][2], bl[pr][3], rbb + GT_TILE_B);
            }
#pragma unroll
            for (int mt = 0; mt < 4; mt++)
#pragma unroll
                for (int nt = 0; nt < 4; nt++) {
                    const int pr = nt >> 1, hl = (nt & 1) << 1;
                    MMA16816(acc[mt][nt], ah[mt][0], ah[mt][1], ah[mt][2], ah[mt][3],
                             bh[pr][hl], bh[pr][hl + 1]);
                    MMA16816(acc[mt][nt], al[mt][0], al[mt][1], al[mt][2], al[mt][3],
                             bh[pr][hl], bh[pr][hl + 1]);
                    MMA16816(acc[mt][nt], ah[mt][0], ah[mt][1], ah[mt][2], ah[mt][3],
                             bl[pr][hl], bl[pr][hl + 1]);
                }
        }
        __syncthreads();
    }

    const int crow = lane >> 2;
    const int ccol = (lane & 3) << 1;
#pragma unroll
    for (int mt = 0; mt < 4; mt++)
#pragma unroll
        for (int nt = 0; nt < 4; nt++) {
            const int r = m0 + wm + mt * 16 + crow;
            const int cc = n0 + wn + nt * 8 + ccol;
            *(float2*)&C[(size_t)r * N + cc]       = make_float2(acc[mt][nt][0], acc[mt][nt][1]);
            *(float2*)&C[(size_t)(r + 8) * N + cc] = make_float2(acc[mt][nt][2], acc[mt][nt][3]);
        }
}

// ---------------------------------------------------------------------------
// In-place RoPE on q and k
// ---------------------------------------------------------------------------
__global__ void rope_kernel(float* __restrict__ q, float* __restrict__ kk,
                            const float* __restrict__ cosb,
                            const float* __restrict__ sinb)
{
    int idx = blockIdx.x * blockDim.x + threadIdx.x;
    const int tq  = S_LEN * NHEADS * 64;
    const int tot = tq + S_LEN * NKV * 64;
    if (idx >= tot) return;

    float* base; int s, rem, stride;
    if (idx < tq) { base = q;  s = idx / (NHEADS * 64); rem = idx % (NHEADS * 64); stride = DMODEL; }
    else { int j = idx - tq; base = kk; s = j / (NKV * 64); rem = j % (NKV * 64); stride = KVDIM; }

    const int i   = rem & 63;
    const int off = s * stride + (rem >> 6) * HDIM + (i << 1);
    const float c  = cosb[s * 64 + i];
    const float sn = sinb[s * 64 + i];
    const float xr = base[off], xi = base[off + 1];
    base[off]     = xr * c - xi * sn;
    base[off + 1] = xr * sn + xi * c;
}

// ---------------------------------------------------------------------------
// Tensor-core flash attention (split-bf16 everywhere), causal, GQA
// CTA: 256 thr / 8 warps; q-tile 128 (warp owns 16 rows); kv-tile 64.
// smem rows: 256B data @272B stride (17 granules, odd -> conflict-free).
// ---------------------------------------------------------------------------
#define AT_QSZ   (128 * 272)          // 34816 per Q tile (h or l)
#define AT_KVSZ  (64 * 272)           // 17408 per K/V tile
#define AT_STAGE (4 * AT_KVSZ)        // Kh,Kl,Vh,Vl = 69632
#define AT_SMEM  (2 * AT_QSZ + 2 * AT_STAGE)   // 208896

__global__ __launch_bounds__(256, 1) void attn_mma(
    const __nv_bfloat16* __restrict__ qh, const __nv_bfloat16* __restrict__ ql,
    const __nv_bfloat16* __restrict__ kh, const __nv_bfloat16* __restrict__ kl,
    const __nv_bfloat16* __restrict__ vh, const __nv_bfloat16* __restrict__ vl,
    float* __restrict__ out)
{
    extern __shared__ char smem[];
    const uint32_t sb = smem_u32(smem);
    const int tid = threadIdx.x, wid = tid >> 5, lane = tid & 31;
    const int h   = blockIdx.y;
    const int qt  = (int)(gridDim.x - 1 - blockIdx.x);   // big tiles first
    const int kvh = h >> 2;
    const int q0  = qt * 128;
    const float scale = 0.08838834764831845f;

    // ---- load Q tiles + kv tile 0, one cp.async group --------------------
    {
        const __nv_bfloat16* qs[2] = {qh, ql};
#pragma unroll
        for (int tI = 0; tI < 2; tI++)
#pragma unroll
            for (int i = 0; i < 8; i++) {
                int g = tid + (i << 8);              // 0..2047
                int row = g >> 4, col = (g & 15) << 4;
                const char* src = (const char*)qs[tI]
                    + ((size_t)(q0 + row) * DMODEL + h * HDIM) * 2 + col;
                CP_ASYNC16(sb + tI * AT_QSZ + row * 272 + col, src);
            }
    }
    const __nv_bfloat16* kvs[4] = {kh, kl, vh, vl};
    auto load_kv = [&](int t, uint32_t stage) {
        const int kv0 = t * 64;
#pragma unroll
        for (int i = 0; i < 16; i++) {
            int tI = i >> 2;
            int g  = tid + ((i & 3) << 8);           // 0..1023
            int row = g >> 4, col = (g & 15) << 4;
            const char* src = (const char*)kvs[tI]
                + ((size_t)(kv0 + row) * KVDIM + kvh * HDIM) * 2 + col;
            CP_ASYNC16(stage + tI * AT_KVSZ + row * 272 + col, src);
        }
    };
    load_kv(0, sb + 2 * AT_QSZ);
    CP_COMMIT();

    // ---- per-thread state -------------------------------------------------
    float Oa[16][4];
#pragma unroll
    for (int d = 0; d < 16; d++)
#pragma unroll
        for (int r = 0; r < 4; r++) Oa[d][r] = 0.f;
    float mrow[2] = {-1e30f, -1e30f}, lrow[2] = {0.f, 0.f};

    const int g_  = lane >> 2, tq_ = lane & 3;
    const int lm  = lane & 7,  grp = lane >> 3;
    const int qa_row  = wid * 16 + (lane & 15);
    const int qa_colg = (lane >> 4) << 4;
    const int kb_row  = ((grp >> 1) << 3) + lm;      // + np*16
    const int kb_colg = (grp & 1) << 4;              // + ks*32
    const int vb_row  = (lane & 7) + (((lane >> 3) & 1) << 3);  // + kk*16
    const int vb_colg = (lane >> 4) << 4;            // + dp*32

    const int tmax = 2 * qt + 1;

    for (int t = 0; t <= tmax; t++) {
        const uint32_t st = sb + 2 * AT_QSZ + (uint32_t)(t & 1) * AT_STAGE;
        if (t < tmax) {
            load_kv(t + 1, sb + 2 * AT_QSZ + (uint32_t)((t + 1) & 1) * AT_STAGE);
            CP_COMMIT();
            CP_WAIT1();
        } else {
            CP_WAIT0();
        }
        __syncthreads();

        const int kv0 = t * 64;
        const bool active = (kv0 <= q0 + wid * 16 + 15);
        if (active) {
            // ---- S = Q K^T (3-term split) --------------------------------
            float S[8][4];
#pragma unroll
            for (int nt = 0; nt < 8; nt++)
#pragma unroll
                for (int r = 0; r < 4; r++) S[nt][r] = 0.f;

#pragma unroll
            for (int ks = 0; ks < 8; ks++) {
                const uint32_t qaddr = sb + qa_row * 272 + (ks << 5) + qa_colg;
                uint32_t qh0, qh1, qh2, qh3, ql0, ql1, ql2, ql3;
                LDSM4(qh0, qh1, qh2, qh3, qaddr);
                LDSM4(ql0, ql1, ql2, ql3, qaddr + AT_QSZ);
#pragma unroll
                for (int np = 0; np < 4; np++) {
                    const uint32_t kaddr = st + (np * 16 + kb_row) * 272 + (ks << 5) + kb_colg;
                    uint32_t k0, k1, k2, k3;
                    LDSM4(k0, k1, k2, k3, kaddr);                 // Kh
                    MMA16816(S[2 * np],     qh0, qh1, qh2, qh3, k0, k1);
                    MMA16816(S[2 * np],     ql0, ql1, ql2, ql3, k0, k1);
                    MMA16816(S[2 * np + 1], qh0, qh1, qh2, qh3, k2, k3);
                    MMA16816(S[2 * np + 1], ql0, ql1, ql2, ql3, k2, k3);
                    LDSM4(k0, k1, k2, k3, kaddr + AT_KVSZ);       // Kl
                    MMA16816(S[2 * np],     qh0, qh1, qh2, qh3, k0, k1);
                    MMA16816(S[2 * np + 1], qh0, qh1, qh2, qh3, k2, k3);
                }
            }

            // ---- online softmax ------------------------------------------
            const bool masked = (kv0 + 63 > q0);
#pragma unroll
            for (int i = 0; i < 2; i++) {
                const int row = q0 + wid * 16 + g_ + 8 * i;
                float mx = -1e30f;
#pragma unroll
                for (int nt = 0; nt < 8; nt++)
#pragma unroll
                    for (int j = 0; j < 2; j++) {
                        float v = S[nt][2 * i + j] * scale;
                        if (masked && (kv0 + nt * 8 + 2 * tq_ + j > row)) v = -1e30f;
                        S[nt][2 * i + j] = v;
                        mx = fmaxf(mx, v);
                    }
                mx = fmaxf(mx, __shfl_xor_sync(0xffffffffu, mx, 1));
                mx = fmaxf(mx, __shfl_xor_sync(0xffffffffu, mx, 2));
                const float mn = fmaxf(mrow[i], mx);
                const float cf = __expf(mrow[i] - mn);
                mrow[i] = mn;
                float rs = 0.f;
#pragma unroll
                for (int nt = 0; nt < 8; nt++)
#pragma unroll
                    for (int j = 0; j < 2; j++) {
                        float p = __expf(S[nt][2 * i + j] - mn);
                        S[nt][2 * i + j] = p;
                        rs += p;
                    }
                rs += __shfl_xor_sync(0xffffffffu, rs, 1);
                rs += __shfl_xor_sync(0xffffffffu, rs, 2);
                lrow[i] = lrow[i] * cf + rs;
#pragma unroll
                for (int d = 0; d < 16; d++) {
                    Oa[d][2 * i + 0] *= cf;
                    Oa[d][2 * i + 1] *= cf;
                }
            }

            // ---- P -> split bf16 A-fragments -----------------------------
            uint32_t Pha[4][4], Pla[4][4];
#pragma unroll
            for (int kk = 0; kk < 4; kk++) {
                splitpack(S[2 * kk][0],     S[2 * kk][1],     Pha[kk][0], Pla[kk][0]);
                splitpack(S[2 * kk][2],     S[2 * kk][3],     Pha[kk][1], Pla[kk][1]);
                splitpack(S[2 * kk + 1][0], S[2 * kk + 1][1], Pha[kk][2], Pla[kk][2]);
                splitpack(S[2 * kk + 1][2], S[2 * kk + 1][3], Pha[kk][3], Pla[kk][3]);
            }

            // ---- O += P V (3-term split) ---------------------------------
#pragma unroll
            for (int dp = 0; dp < 8; dp++) {
#pragma unroll
                for (int kk = 0; kk < 4; kk++) {
                    const uint32_t vaddr = st + 2 * AT_KVSZ
                        + (kk * 16 + vb_row) * 272 + (dp << 5) + vb_colg;
                    uint32_t v0, v1, v2, v3;
                    LDSM4T(v0, v1, v2, v3, vaddr);                // Vh
                    MMA16816(Oa[2 * dp],     Pha[kk][0], Pha[kk][1], Pha[kk][2], Pha[kk][3], v0, v1);
                    MMA16816(Oa[2 * dp + 1], Pha[kk][0], Pha[kk][1], Pha[kk][2], Pha[kk][3], v2, v3);
                    MMA16816(Oa[2 * dp],     Pla[kk][0], Pla[kk][1], Pla[kk][2], Pla[kk][3], v0, v1);
                    MMA16816(Oa[2 * dp + 1], Pla[kk][0], Pla[kk][1], Pla[kk][2], Pla[kk][3], v2, v3);
                    LDSM4T(v0, v1, v2, v3, vaddr + AT_KVSZ);      // Vl
                    MMA16816(Oa[2 * dp],     Pha[kk][0], Pha[kk][1], Pha[kk][2], Pha[kk][3], v0, v1);
                    MMA16816(Oa[2 * dp + 1], Pha[kk][0], Pha[kk][1], Pha[kk][2], Pha[kk][3], v2, v3);
                }
            }
        }
        __syncthreads();
    }

    // ---- epilogue ----------------------------------------------------------
#pragma unroll
    for (int i = 0; i < 2; i++) {
        const float inv = 1.0f / lrow[i];
        const int row = q0 + wid * 16 + g_ + 8 * i;
#pragma unroll
        for (int d = 0; d < 16; d++) {
            float2 vv = make_float2(Oa[d][2 * i] * inv, Oa[d][2 * i + 1] * inv);
            *(float2*)&out[(size_t)row * DMODEL + h * HDIM + d * 8 + 2 * tq_] = vv;
        }
    }
}

// ---------------------------------------------------------------------------
extern "C" void kernel_launch(void* const* d_in, const int* in_sizes, int n_in,
                              void* d_out, int out_size)
{
    const float* x    = (const float*)d_in[0];
    const float* wq   = (const float*)d_in[1];
    const float* wk   = (const float*)d_in[2];
    const float* wv   = (const float*)d_in[3];
    const float* wo   = (const float*)d_in[4];
    const float* cosb = (const float*)d_in[7];
    const float* sinb = (const float*)d_in[8];
    float* out = (float*)d_out;

    float *q, *k, *v, *a;
    cudaGetSymbolAddress((void**)&q, g_q);
    cudaGetSymbolAddress((void**)&k, g_k);
    cudaGetSymbolAddress((void**)&v, g_v);
    cudaGetSymbolAddress((void**)&a, g_a);
    __nv_bfloat16 *xh, *xl, *ah, *al, *wqh, *wql, *wkh, *wkl, *wvh, *wvl, *woh, *wol;
    __nv_bfloat16 *qh2, *ql2, *kh2, *kl2, *vh2, *vl2;
    cudaGetSymbolAddress((void**)&xh, g_xh);   cudaGetSymbolAddress((void**)&xl, g_xl);
    cudaGetSymbolAddress((void**)&ah, g_ah);   cudaGetSymbolAddress((void**)&al, g_al);
    cudaGetSymbolAddress((void**)&wqh, g_wqh); cudaGetSymbolAddress((void**)&wql, g_wql);
    cudaGetSymbolAddress((void**)&wkh, g_wkh); cudaGetSymbolAddress((void**)&wkl, g_wkl);
    cudaGetSymbolAddress((void**)&wvh, g_wvh); cudaGetSymbolAddress((void**)&wvl, g_wvl);
    cudaGetSymbolAddress((void**)&woh, g_woh); cudaGetSymbolAddress((void**)&wol, g_wol);
    cudaGetSymbolAddress((void**)&qh2, g_qh2); cudaGetSymbolAddress((void**)&ql2, g_ql2);
    cudaGetSymbolAddress((void**)&kh2, g_kh2); cudaGetSymbolAddress((void**)&kl2, g_kl2);
    cudaGetSymbolAddress((void**)&vh2, g_vh2); cudaGetSymbolAddress((void**)&vl2, g_vl2);

    cudaFuncSetAttribute(gemm_mma, cudaFuncAttributeMaxDynamicSharedMemorySize, GT_SMEM_B);
    cudaFuncSetAttribute(attn_mma, cudaFuncAttributeMaxDynamicSharedMemorySize, AT_SMEM);

    const int nx = S_LEN * DMODEL, nwq = DMODEL * DMODEL, nwk = KVDIM * DMODEL;
    const int nkv = S_LEN * KVDIM;
    split_kernel<<<nx  / 1024, 256>>>(x,  xh,  xl,  nx);
    split_kernel<<<nwq / 1024, 256>>>(wq, wqh, wql, nwq);
    split_kernel<<<nwk / 1024, 256>>>(wk, wkh, wkl, nwk);
    split_kernel<<<nwk / 1024, 256>>>(wv, wvh, wvl, nwk);
    split_kernel<<<nwq / 1024, 256>>>(wo, woh, wol, nwq);

    gemm_mma<<<dim3(DMODEL / 128, S_LEN / 128), 256, GT_SMEM_B>>>(xh, xl, wqh, wql, q, DMODEL, DMODEL);
    gemm_mma<<<dim3(KVDIM  / 128, S_LEN / 128), 256, GT_SMEM_B>>>(xh, xl, wkh, wkl, k, KVDIM,  DMODEL);
    gemm_mma<<<dim3(KVDIM  / 128, S_LEN / 128), 256, GT_SMEM_B>>>(xh, xl, wvh, wvl, v, KVDIM,  DMODEL);

    const int pairs = S_LEN * NHEADS * 64 + S_LEN * NKV * 64;
    rope_kernel<<<(pairs + 255) / 256, 256>>>(q, k, cosb, sinb);

    // split post-RoPE q/k and v for the tensor attention
    split_kernel<<<nx  / 1024, 256>>>(q, qh2, ql2, nx);
    split_kernel<<<nkv / 1024, 256>>>(k, kh2, kl2, nkv);
    split_kernel<<<nkv / 1024, 256>>>(v, vh2, vl2, nkv);

    attn_mma<<<dim3(S_LEN / 128, NHEADS), 256, AT_SMEM>>>(qh2, ql2, kh2, kl2, vh2, vl2, a);

    split_kernel<<<nx / 1024, 256>>>(a, ah, al, nx);
    gemm_mma<<<dim3(DMODEL / 128, S_LEN / 128), 256, GT_SMEM_B>>>(ah, al, woh, wol, out, DMODEL, DMODEL);
}